// round 13
// baseline (speedup 1.0000x reference)
#include <cuda_runtime.h>
#include <cstdint>

#define Bn 16
#define Ln 65536
#define Hn 64
#define Kn 64
#define LOUT (Ln - Hn + 1)              /* 65473 */
#define TILE_M 256
#define NTILES ((LOUT + TILE_M - 1) / TILE_M)   /* 256 */
#define THREADS 256                      /* 8 warps, each M=32 x N=64 */

// ---- dynamic SMEM layout (bytes) ----
#define OFF_S     0          /* 64 floats: S_k */
#define OFF_BV    256        /* 64 floats: b_k */
#define OFF_INV   512        /* 256 floats: 1/(sd+eps) */
#define OFF_MUI   1536       /* 256 floats: mu*inv */
#define OFF_XS    2560       /* 328 floats: tf32-rounded x window */
#define OFF_XS2   3872       /* 320 float2: {xs[i], xs[i+4]} pairs */
#define OFF_W     6432       /* 64 rows x 272B (68 words: 4 mod 32 -> bank-clean) */
// epilogue staging overlays W/xs (dead after MMA + barrier): 8 warps x 4608B
#define OFF_STAGE OFF_W
#define WSTAGE    4608       /* 16 rows * 72 words * 4B per warp */
#define SMEM_BYTES (OFF_STAGE + 8 * WSTAGE)   /* 43296 */

__device__ float2 g_Wp[Kn * 32];   // [n][kk*4+ct] = {W~[n][kk*8+ct], W~[n][kk*8+ct+4]}
__device__ float  g_S[Kn];

__device__ __forceinline__ float tf32r(float v) {
    uint32_t t;
    asm("cvt.rna.tf32.f32 %0, %1;" : "=r"(t) : "f"(v));
    return __uint_as_float(t);
}

__device__ __forceinline__ void mma_tf32(float* c, const uint32_t* a,
                                         uint32_t b0, uint32_t b1) {
    asm volatile(
        "mma.sync.aligned.m16n8k8.row.col.f32.tf32.tf32.f32 "
        "{%0,%1,%2,%3}, {%4,%5,%6,%7}, {%8,%9}, {%0,%1,%2,%3};"
        : "+f"(c[0]), "+f"(c[1]), "+f"(c[2]), "+f"(c[3])
        : "r"(a[0]), "r"(a[1]), "r"(a[2]), "r"(a[3]), "r"(b0), "r"(b1));
}

// prep: blocks 0..7 build permuted tf32 W + S_k; block 8 fills tuple tail
__global__ void prep_kernel(const float* __restrict__ W, float* __restrict__ out,
                            long long expected, int extra) {
    if (blockIdx.x == 8) {
        for (int i = threadIdx.x; i < extra; i += blockDim.x)
            out[expected + i] = 63.0f;   // warmup scalar
        return;
    }
    int i = blockIdx.x * blockDim.x + threadIdx.x;   // 0..2047
    int lane = i & 31;
    {
        int n = i >> 5, r = i & 31, kk = r >> 2, ct = r & 3;
        float2 p;
        p.x = tf32r(W[n * Hn + kk * 8 + ct]);
        p.y = tf32r(W[n * Hn + kk * 8 + ct + 4]);
        g_Wp[i] = p;
    }
    {
        int row = i >> 5;   // 0..63, one warp per k-row
        float v = tf32r(W[row * Hn + lane]) + tf32r(W[row * Hn + 32 + lane]);
#pragma unroll
        for (int o = 16; o > 0; o >>= 1)
            v += __shfl_xor_sync(0xFFFFFFFFu, v, o);
        if (lane == 0) g_S[row] = v;
    }
}

__global__ void __launch_bounds__(THREADS, 2)
hankel_filterbank_kernel(const float* __restrict__ x,
                         const float* __restrict__ bv,
                         float* __restrict__ out)
{
    extern __shared__ char sm[];
    const int tid = threadIdx.x;
    const int wid = tid >> 5;
    const int lid = tid & 31;
    const int g   = lid >> 2;     // group id 0..7
    const int ct  = lid & 3;      // thread-in-group
    const int t0  = (blockIdx.x & (NTILES - 1)) * TILE_M;
    const int batch = blockIdx.x >> 8;   // NTILES == 256

    float* xs   = (float*)(sm + OFF_XS);
    float2* xs2 = (float2*)(sm + OFF_XS2);

    // ---- stage + tf32-round x window (zero past end) ----
    const float* xb = x + (size_t)batch * Ln;
#pragma unroll
    for (int i = tid; i < 328; i += THREADS) {
        int gi = t0 + i;
        xs[i] = (gi < Ln) ? tf32r(xb[gi]) : 0.0f;
    }

    // ---- copy permuted tf32 W into 272B rows (bank-clean stride) ----
    {
        const float4* src = (const float4*)g_Wp;
#pragma unroll
        for (int j = tid; j < 1024; j += THREADS) {
            int n = j >> 4, q = j & 15;
            *(float4*)(sm + OFF_W + n * 272 + q * 16) = src[j];
        }
    }
    if (tid < Kn) {
        ((float*)(sm + OFF_S))[tid]  = g_S[tid];
        ((float*)(sm + OFF_BV))[tid] = bv[tid];
    }
    __syncthreads();

    // ---- xs2 pairs; per-row stats (row = tid) ----
#pragma unroll
    for (int i = tid; i < 320; i += THREADS) {
        float2 p;
        p.x = xs[i];
        p.y = xs[i + 4];
        xs2[i] = p;
    }
    {
        float sum = 0.0f, sq = 0.0f;
#pragma unroll
        for (int h = 0; h < Hn; ++h) {
            float v = xs[tid + h];
            sum += v;
            sq = fmaf(v, v, sq);
        }
        float mu  = sum * (1.0f / 64.0f);
        float var = fmaxf(sq - sum * mu, 0.0f) * (1.0f / 63.0f);
        float inv = 1.0f / (sqrtf(var) + 1e-6f);
        ((float*)(sm + OFF_INV))[tid] = inv;
        ((float*)(sm + OFF_MUI))[tid] = mu * inv;
    }
    __syncthreads();

    // ---- A-fragment register cache: sliding window across kk ----
    // aA0(kk)=v[kk], aB0=v[kk+1], aA1=v[kk+2], aB1=v[kk+3]
    const int Rw = wid << 5;   // warp row base within tile
    float2 v[11];
#pragma unroll
    for (int j = 0; j < 11; ++j) v[j] = xs2[Rw + g + ct + 8 * j];

    float c[2][8][4];
#pragma unroll
    for (int mb = 0; mb < 2; ++mb)
#pragma unroll
        for (int nb = 0; nb < 8; ++nb)
#pragma unroll
            for (int r = 0; r < 4; ++r) c[mb][nb][r] = 0.0f;

#pragma unroll
    for (int kk = 0; kk < 8; ++kk) {
        uint32_t a0[4] = { __float_as_uint(v[kk].x),     __float_as_uint(v[kk + 1].x),
                           __float_as_uint(v[kk].y),     __float_as_uint(v[kk + 1].y) };
        uint32_t a1[4] = { __float_as_uint(v[kk + 2].x), __float_as_uint(v[kk + 3].x),
                           __float_as_uint(v[kk + 2].y), __float_as_uint(v[kk + 3].y) };
#pragma unroll
        for (int nb = 0; nb < 8; ++nb) {
            int n = (nb << 3) + g;
            float2 bb = *(const float2*)(sm + OFF_W + n * 272 + (kk * 4 + ct) * 8);
            uint32_t b0 = __float_as_uint(bb.x), b1 = __float_as_uint(bb.y);
            mma_tf32(c[0][nb], a0, b0, b1);
            mma_tf32(c[1][nb], a1, b0, b1);
        }
    }

    __syncthreads();   // all W/xs reads done; staging region becomes free

    // ---- epilogue: stride-72 staging (bank-clean), dense STG.128 ----
    const float* Ss  = (const float*)(sm + OFF_S);
    const float* bs  = (const float*)(sm + OFF_BV);
    const float* inv = (const float*)(sm + OFF_INV);
    const float* mui = (const float*)(sm + OFF_MUI);
    float* stw  = (float*)(sm + OFF_STAGE + wid * WSTAGE);
    float* outb = out + (size_t)batch * LOUT * Kn;

#pragma unroll
    for (int mb = 0; mb < 2; ++mb) {
        const int rA = Rw + (mb << 4) + g;
        const float iA = inv[rA],     mA = mui[rA];
        const float iB = inv[rA + 8], mB = mui[rA + 8];
#pragma unroll
        for (int nb = 0; nb < 8; ++nb) {
            int col = (nb << 3) + (ct << 1);
            float2 S2 = *(const float2*)(Ss + col);
            float2 b2 = *(const float2*)(bs + col);
            float2 yA, yB;
            yA.x = fmaxf(fmaf(c[mb][nb][0], iA, fmaf(-mA, S2.x, b2.x)), 0.0f);
            yA.y = fmaxf(fmaf(c[mb][nb][1], iA, fmaf(-mA, S2.y, b2.y)), 0.0f);
            yB.x = fmaxf(fmaf(c[mb][nb][2], iB, fmaf(-mB, S2.x, b2.x)), 0.0f);
            yB.y = fmaxf(fmaf(c[mb][nb][3], iB, fmaf(-mB, S2.y, b2.y)), 0.0f);
            *(float2*)(stw + g * 72 + col)       = yA;   // 16 rows x 64 cols
            *(float2*)(stw + (g + 8) * 72 + col) = yB;   // stride 72: bank-clean
        }
        __syncwarp();

        // dense streaming stores: lanes 0-15 -> one row's 256B, 16-31 -> next
#pragma unroll
        for (int i = 0; i < 8; ++i) {
            int row  = (i << 1) + (lid >> 4);
            int quad = lid & 15;
            int gr = t0 + Rw + (mb << 4) + row;
            if (gr < LOUT) {
                float4 val = *(const float4*)(stw + row * 72 + (quad << 2));
                __stcs((float4*)(outb + (size_t)gr * Kn + (quad << 2)), val);
            }
        }
        __syncwarp();
    }
}

extern "C" void kernel_launch(void* const* d_in, const int* in_sizes, int n_in,
                              void* d_out, int out_size) {
    const float* x  = (const float*)d_in[0];
    const float* W  = (const float*)d_in[1];
    const float* bv = (const float*)d_in[2];
    float* out = (float*)d_out;

    long long expected = (long long)Bn * LOUT * Kn;
    int extra = ((long long)out_size > expected)
                    ? (int)((long long)out_size - expected) : 0;

    prep_kernel<<<9, 256>>>(W, out, expected, extra);

    cudaFuncSetAttribute(hankel_filterbank_kernel,
                         cudaFuncAttributeMaxDynamicSharedMemorySize, SMEM_BYTES);
    hankel_filterbank_kernel<<<NTILES * Bn, THREADS, SMEM_BYTES>>>(x, bv, out);
}

// round 14
// speedup vs baseline: 1.1045x; 1.1045x over previous
#include <cuda_runtime.h>
#include <cstdint>

#define Bn 16
#define Ln 65536
#define Hn 64
#define Kn 64
#define LOUT (Ln - Hn + 1)              /* 65473 */
#define TILE_M 256
#define NTILES ((LOUT + TILE_M - 1) / TILE_M)   /* 256 */
#define THREADS 256                      /* 8 warps, each M=32 x N=64 */

// ---- dynamic SMEM layout (bytes) ----
#define OFF_S     0          /* 64 floats: S_k */
#define OFF_BV    256        /* 64 floats: b_k */
#define OFF_INV   512        /* 256 floats: 1/(sd+eps) */
#define OFF_MUI   1536       /* 256 floats: mu*inv */
#define OFF_WT    2560       /* 8 float2: per-warp scan totals */
#define OFF_WO    2624       /* 8 float2: per-warp scan offsets */
#define OFF_SC    2688       /* 257 float2: prefix {sum,sumsq}, 2056B */
#define OFF_XS    4768       /* 512 floats: tf32-rounded x window (padded) */
#define OFF_W     6816       /* 64 rows x 320B (80 words: 16 mod 32) = 20480 */
// epilogue staging overlays W (dead after MMA + barrier): 8 warps x 4608B
#define OFF_STAGE OFF_W
#define WSTAGE    4608       /* 16 rows * 72 words * 4B per warp */
#define SMEM_BYTES (OFF_STAGE + 8 * WSTAGE)   /* 43680 */

__device__ float4 g_Wp[Kn * 16];   // [n][kk2*4+ct] = pairs for kk=2kk2 and 2kk2+1
__device__ float  g_S[Kn];

__device__ __forceinline__ float tf32r(float v) {
    uint32_t t;
    asm("cvt.rna.tf32.f32 %0, %1;" : "=r"(t) : "f"(v));
    return __uint_as_float(t);
}

__device__ __forceinline__ void mma_tf32(float* c, const uint32_t* a,
                                         uint32_t b0, uint32_t b1) {
    asm volatile(
        "mma.sync.aligned.m16n8k8.row.col.f32.tf32.tf32.f32 "
        "{%0,%1,%2,%3}, {%4,%5,%6,%7}, {%8,%9}, {%0,%1,%2,%3};"
        : "+f"(c[0]), "+f"(c[1]), "+f"(c[2]), "+f"(c[3])
        : "r"(a[0]), "r"(a[1]), "r"(a[2]), "r"(a[3]), "r"(b0), "r"(b1));
}

// prep: blocks 0..7 build grouped tf32 W + S_k; block 8 fills tuple tail
__global__ void prep_kernel(const float* __restrict__ W, float* __restrict__ out,
                            long long expected, int extra) {
    if (blockIdx.x == 8) {
        for (int i = threadIdx.x; i < extra; i += blockDim.x)
            out[expected + i] = 63.0f;   // warmup scalar
        return;
    }
    int i = blockIdx.x * blockDim.x + threadIdx.x;   // 0..2047
    int lane = i & 31;
    if (i < Kn * 16) {
        int n = i >> 4, r = i & 15, kk2 = r >> 2, ct = r & 3;
        const float* wr = W + n * Hn + kk2 * 16 + ct;
        float4 p;
        p.x = tf32r(wr[0]);   p.y = tf32r(wr[4]);    // kk = 2*kk2
        p.z = tf32r(wr[8]);   p.w = tf32r(wr[12]);   // kk = 2*kk2+1
        g_Wp[i] = p;
    }
    {
        int row = i >> 5;   // 0..63, one warp per k-row
        float v = tf32r(W[row * Hn + lane]) + tf32r(W[row * Hn + 32 + lane]);
#pragma unroll
        for (int o = 16; o > 0; o >>= 1)
            v += __shfl_xor_sync(0xFFFFFFFFu, v, o);
        if (lane == 0) g_S[row] = v;
    }
}

__global__ void __launch_bounds__(THREADS, 2)
hankel_filterbank_kernel(const float* __restrict__ x,
                         const float* __restrict__ bv,
                         float* __restrict__ out)
{
    extern __shared__ char sm[];
    const int tid = threadIdx.x;
    const int wid = tid >> 5;
    const int lid = tid & 31;
    const int g   = lid >> 2;     // group id 0..7
    const int ct  = lid & 3;      // thread-in-group
    const int t0  = (blockIdx.x & (NTILES - 1)) * TILE_M;
    const int batch = blockIdx.x >> 8;   // NTILES == 256

    float* xs = (float*)(sm + OFF_XS);

    // ---- stage + tf32-round x window (512 slots, zero past end) ----
    const float* xb = x + (size_t)batch * Ln;
#pragma unroll
    for (int i = tid; i < 512; i += THREADS) {
        int gi = t0 + i;
        xs[i] = (gi < Ln) ? tf32r(xb[gi]) : 0.0f;
    }

    // ---- copy grouped tf32 W into 320B rows (LDS.128 bank-clean) ----
    {
#pragma unroll
        for (int j = tid; j < 1024; j += THREADS) {
            int n = j >> 4, q = j & 15;
            *(float4*)(sm + OFF_W + n * 320 + q * 16) = g_Wp[j];
        }
    }
    if (tid < Kn) {
        ((float*)(sm + OFF_S))[tid]  = g_S[tid];
        ((float*)(sm + OFF_BV))[tid] = bv[tid];
    }
    __syncthreads();

    // ---- block prefix scan of {sum, sumsq}: 2 elements per thread ----
    float2* sc = (float2*)(sm + OFF_SC);
    {
        float x0 = xs[2 * tid], x1 = xs[2 * tid + 1];
        float pS = x0 + x1;
        float pQ = fmaf(x0, x0, x1 * x1);
#pragma unroll
        for (int o = 1; o < 32; o <<= 1) {
            float tS = __shfl_up_sync(0xFFFFFFFFu, pS, o);
            float tQ = __shfl_up_sync(0xFFFFFFFFu, pQ, o);
            if (lid >= o) { pS += tS; pQ += tQ; }
        }
        if (lid == 31) {
            float2 t; t.x = pS; t.y = pQ;
            ((float2*)(sm + OFF_WT))[wid] = t;
        }
        __syncthreads();
        if (tid < 8) {
            float s = 0.0f, q = 0.0f;
            for (int j = 0; j < tid; ++j) {
                float2 t = ((const float2*)(sm + OFF_WT))[j];
                s += t.x; q += t.y;
            }
            float2 o; o.x = s; o.y = q;
            ((float2*)(sm + OFF_WO))[tid] = o;
        }
        __syncthreads();
        float2 off = ((const float2*)(sm + OFF_WO))[wid];
        float2 e; e.x = off.x + pS; e.y = off.y + pQ;
        sc[tid + 1] = e;              // P[2*(tid+1)] inclusive of 2tid+1
        if (tid == 0) { float2 z; z.x = 0.0f; z.y = 0.0f; sc[0] = z; }
    }
    __syncthreads();

    // ---- per-row stats from prefix differences (row = tid) ----
    {
        const int m = tid;
        float S, Q;
        if (!(m & 1)) {
            float2 a = sc[m >> 1], b2 = sc[(m + 64) >> 1];
            S = b2.x - a.x;  Q = b2.y - a.y;
        } else {
            float xa = xs[m - 1], xb2 = xs[m + 63];
            float2 a = sc[(m - 1) >> 1], b2 = sc[(m + 63) >> 1];
            S = (b2.x + xb2) - (a.x + xa);
            Q = (b2.y + xb2 * xb2) - (a.y + xa * xa);
        }
        float mu  = S * (1.0f / 64.0f);
        float var = fmaxf(Q - S * mu, 0.0f) * (1.0f / 63.0f);
        float inv = 1.0f / (sqrtf(var) + 1e-6f);
        ((float*)(sm + OFF_INV))[tid] = inv;
        ((float*)(sm + OFF_MUI))[tid] = mu * inv;
    }
    __syncthreads();

    // ---- A-fragment register cache: sliding window across kk ----
    const int Rw = wid << 5;   // warp row base within tile
    const int vb = Rw + g + ct;
    float2 v[11];
#pragma unroll
    for (int j = 0; j < 11; ++j) {
        v[j].x = xs[vb + 8 * j];
        v[j].y = xs[vb + 8 * j + 4];
    }

    float c[2][8][4];
#pragma unroll
    for (int mb = 0; mb < 2; ++mb)
#pragma unroll
        for (int nb = 0; nb < 8; ++nb)
#pragma unroll
            for (int r = 0; r < 4; ++r) c[mb][nb][r] = 0.0f;

    // ---- mainloop: 32 LDS.128 (conflict-free) + 128 HMMA per thread ----
#pragma unroll
    for (int kk2 = 0; kk2 < 4; ++kk2) {
        const int k0 = 2 * kk2;
        uint32_t a0[4]  = { __float_as_uint(v[k0].x),     __float_as_uint(v[k0 + 1].x),
                            __float_as_uint(v[k0].y),     __float_as_uint(v[k0 + 1].y) };
        uint32_t a0b[4] = { __float_as_uint(v[k0 + 1].x), __float_as_uint(v[k0 + 2].x),
                            __float_as_uint(v[k0 + 1].y), __float_as_uint(v[k0 + 2].y) };
        uint32_t a1[4]  = { __float_as_uint(v[k0 + 2].x), __float_as_uint(v[k0 + 3].x),
                            __float_as_uint(v[k0 + 2].y), __float_as_uint(v[k0 + 3].y) };
        uint32_t a1b[4] = { __float_as_uint(v[k0 + 3].x), __float_as_uint(v[k0 + 4].x),
                            __float_as_uint(v[k0 + 3].y), __float_as_uint(v[k0 + 4].y) };
#pragma unroll
        for (int nb = 0; nb < 8; ++nb) {
            int n = (nb << 3) + g;
            float4 bb = *(const float4*)(sm + OFF_W + n * 320 + kk2 * 64 + ct * 16);
            uint32_t b0 = __float_as_uint(bb.x), b1 = __float_as_uint(bb.y);
            uint32_t b2 = __float_as_uint(bb.z), b3 = __float_as_uint(bb.w);
            mma_tf32(c[0][nb], a0,  b0, b1);
            mma_tf32(c[0][nb], a0b, b2, b3);
            mma_tf32(c[1][nb], a1,  b0, b1);
            mma_tf32(c[1][nb], a1b, b2, b3);
        }
    }

    __syncthreads();   // all W/xs reads done; staging region becomes free

    // ---- epilogue: stride-72 staging (bank-clean), dense STG.128 ----
    const float* Ss  = (const float*)(sm + OFF_S);
    const float* bs  = (const float*)(sm + OFF_BV);
    const float* inv = (const float*)(sm + OFF_INV);
    const float* mui = (const float*)(sm + OFF_MUI);
    float* stw  = (float*)(sm + OFF_STAGE + wid * WSTAGE);
    float* outb = out + (size_t)batch * LOUT * Kn;

#pragma unroll
    for (int mb = 0; mb < 2; ++mb) {
        const int rA = Rw + (mb << 4) + g;
        const float iA = inv[rA],     mA = mui[rA];
        const float iB = inv[rA + 8], mB = mui[rA + 8];
#pragma unroll
        for (int nb = 0; nb < 8; ++nb) {
            int col = (nb << 3) + (ct << 1);
            float2 S2 = *(const float2*)(Ss + col);
            float2 b2 = *(const float2*)(bs + col);
            float2 yA, yB;
            yA.x = fmaxf(fmaf(c[mb][nb][0], iA, fmaf(-mA, S2.x, b2.x)), 0.0f);
            yA.y = fmaxf(fmaf(c[mb][nb][1], iA, fmaf(-mA, S2.y, b2.y)), 0.0f);
            yB.x = fmaxf(fmaf(c[mb][nb][2], iB, fmaf(-mB, S2.x, b2.x)), 0.0f);
            yB.y = fmaxf(fmaf(c[mb][nb][3], iB, fmaf(-mB, S2.y, b2.y)), 0.0f);
            *(float2*)(stw + g * 72 + col)       = yA;   // 16 rows x 64 cols
            *(float2*)(stw + (g + 8) * 72 + col) = yB;   // stride 72: bank-clean
        }
        __syncwarp();

        // dense streaming stores: lanes 0-15 -> one row's 256B, 16-31 -> next
#pragma unroll
        for (int i = 0; i < 8; ++i) {
            int row  = (i << 1) + (lid >> 4);
            int quad = lid & 15;
            int gr = t0 + Rw + (mb << 4) + row;
            if (gr < LOUT) {
                float4 val = *(const float4*)(stw + row * 72 + (quad << 2));
                __stcs((float4*)(outb + (size_t)gr * Kn + (quad << 2)), val);
            }
        }
        __syncwarp();
    }
}

extern "C" void kernel_launch(void* const* d_in, const int* in_sizes, int n_in,
                              void* d_out, int out_size) {
    const float* x  = (const float*)d_in[0];
    const float* W  = (const float*)d_in[1];
    const float* bv = (const float*)d_in[2];
    float* out = (float*)d_out;

    long long expected = (long long)Bn * LOUT * Kn;
    int extra = ((long long)out_size > expected)
                    ? (int)((long long)out_size - expected) : 0;

    prep_kernel<<<9, 256>>>(W, out, expected, extra);

    cudaFuncSetAttribute(hankel_filterbank_kernel,
                         cudaFuncAttributeMaxDynamicSharedMemorySize, SMEM_BYTES);
    hankel_filterbank_kernel<<<NTILES * Bn, THREADS, SMEM_BYTES>>>(x, bv, out);
}

// round 16
// speedup vs baseline: 1.2837x; 1.1622x over previous
#include <cuda_runtime.h>
#include <cstdint>

#define Bn 16
#define Ln 65536
#define Hn 64
#define Kn 64
#define LOUT (Ln - Hn + 1)              /* 65473 */
#define TILE_M 256
#define NTILES ((LOUT + TILE_M - 1) / TILE_M)   /* 256 */
#define THREADS 256                      /* 8 warps; warp = M32 x N32 x 2 passes */

// ---- dynamic SMEM layout (bytes) ----
#define OFF_S     0          /* 64 floats: S_k */
#define OFF_BV    256        /* 64 floats: b_k */
#define OFF_INV   512        /* 256 floats: 1/(sd+eps) */
#define OFF_MUI   1536       /* 256 floats: mu*inv */
#define OFF_WT    2560       /* 8 float2: per-warp scan totals */
#define OFF_WO    2624       /* 8 float2: per-warp scan offsets */
#define OFF_SC    2688       /* 257 float2: prefix {sum,sumsq} */
#define OFF_XS    4768       /* 512 floats: tf32-rounded x window */
#define OFF_W     6816       /* 64 rows x 320B (80 words: 16 mod 32) = 20480 */
// staging: own region (W stays live through pass 2): 8 warps x 5120B
#define OFF_STAGE (OFF_W + 64 * 320)            /* 27296 */
#define WSTAGE    5120       /* 32 rows * 40 words * 4B per warp */
#define SMEM_BYTES (OFF_STAGE + 8 * WSTAGE)     /* 68256 */

__device__ float4 g_Wp[Kn * 16];   // [n][kk2*4+ct] = pairs for kk=2kk2, 2kk2+1
__device__ float  g_S[Kn];

__device__ __forceinline__ float tf32r(float v) {
    uint32_t t;
    asm("cvt.rna.tf32.f32 %0, %1;" : "=r"(t) : "f"(v));
    return __uint_as_float(t);
}

__device__ __forceinline__ void mma_tf32(float* c, uint32_t a0, uint32_t a1,
                                         uint32_t a2, uint32_t a3,
                                         uint32_t b0, uint32_t b1) {
    asm volatile(
        "mma.sync.aligned.m16n8k8.row.col.f32.tf32.tf32.f32 "
        "{%0,%1,%2,%3}, {%4,%5,%6,%7}, {%8,%9}, {%0,%1,%2,%3};"
        : "+f"(c[0]), "+f"(c[1]), "+f"(c[2]), "+f"(c[3])
        : "r"(a0), "r"(a1), "r"(a2), "r"(a3), "r"(b0), "r"(b1));
}

// prep: blocks 0..7 build grouped tf32 W + S_k; block 8 fills tuple tail
__global__ void prep_kernel(const float* __restrict__ W, float* __restrict__ out,
                            long long expected, int extra) {
    if (blockIdx.x == 8) {
        for (int i = threadIdx.x; i < extra; i += blockDim.x)
            out[expected + i] = 63.0f;   // warmup scalar
        return;
    }
    int i = blockIdx.x * blockDim.x + threadIdx.x;   // 0..2047
    int lane = i & 31;
    if (i < Kn * 16) {
        int n = i >> 4, r = i & 15, kk2 = r >> 2, ct = r & 3;
        const float* wr = W + n * Hn + kk2 * 16 + ct;
        float4 p;
        p.x = tf32r(wr[0]);   p.y = tf32r(wr[4]);    // kk = 2*kk2
        p.z = tf32r(wr[8]);   p.w = tf32r(wr[12]);   // kk = 2*kk2+1
        g_Wp[i] = p;
    }
    {
        int row = i >> 5;   // 0..63, one warp per k-row
        float v = tf32r(W[row * Hn + lane]) + tf32r(W[row * Hn + 32 + lane]);
#pragma unroll
        for (int o = 16; o > 0; o >>= 1)
            v += __shfl_xor_sync(0xFFFFFFFFu, v, o);
        if (lane == 0) g_S[row] = v;
    }
}

__global__ void __launch_bounds__(THREADS, 3)
hankel_filterbank_kernel(const float* __restrict__ x,
                         const float* __restrict__ bv,
                         float* __restrict__ out)
{
    extern __shared__ char sm[];
    const int tid = threadIdx.x;
    const int wid = tid >> 5;
    const int lid = tid & 31;
    const int g   = lid >> 2;     // group id 0..7
    const int ct  = lid & 3;      // thread-in-group
    const int t0  = (blockIdx.x & (NTILES - 1)) * TILE_M;
    const int batch = blockIdx.x >> 8;   // NTILES == 256

    float* xs = (float*)(sm + OFF_XS);

    // ---- stage + tf32-round x window (512 slots, zero past end) ----
    const float* xb = x + (size_t)batch * Ln;
#pragma unroll
    for (int i = tid; i < 512; i += THREADS) {
        int gi = t0 + i;
        xs[i] = (gi < Ln) ? tf32r(xb[gi]) : 0.0f;
    }

    // ---- copy grouped tf32 W into 320B rows (LDS.128 bank-clean) ----
#pragma unroll
    for (int j = tid; j < 1024; j += THREADS) {
        int n = j >> 4, q = j & 15;
        *(float4*)(sm + OFF_W + n * 320 + q * 16) = g_Wp[j];
    }
    if (tid < Kn) {
        ((float*)(sm + OFF_S))[tid]  = g_S[tid];
        ((float*)(sm + OFF_BV))[tid] = bv[tid];
    }
    __syncthreads();

    // ---- block prefix scan of {sum, sumsq}: 2 elements per thread ----
    float2* sc = (float2*)(sm + OFF_SC);
    {
        float x0 = xs[2 * tid], x1 = xs[2 * tid + 1];
        float pS = x0 + x1;
        float pQ = fmaf(x0, x0, x1 * x1);
#pragma unroll
        for (int o = 1; o < 32; o <<= 1) {
            float tS = __shfl_up_sync(0xFFFFFFFFu, pS, o);
            float tQ = __shfl_up_sync(0xFFFFFFFFu, pQ, o);
            if (lid >= o) { pS += tS; pQ += tQ; }
        }
        if (lid == 31) {
            float2 t; t.x = pS; t.y = pQ;
            ((float2*)(sm + OFF_WT))[wid] = t;
        }
        __syncthreads();
        if (tid < 8) {
            float s = 0.0f, q = 0.0f;
            for (int j = 0; j < tid; ++j) {
                float2 t = ((const float2*)(sm + OFF_WT))[j];
                s += t.x; q += t.y;
            }
            float2 o; o.x = s; o.y = q;
            ((float2*)(sm + OFF_WO))[tid] = o;
        }
        __syncthreads();
        float2 off = ((const float2*)(sm + OFF_WO))[wid];
        float2 e; e.x = off.x + pS; e.y = off.y + pQ;
        sc[tid + 1] = e;
        if (tid == 0) { float2 z; z.x = 0.0f; z.y = 0.0f; sc[0] = z; }
    }
    __syncthreads();

    // ---- per-row stats from prefix differences (row = tid) ----
    {
        const int m = tid;
        float S, Q;
        if (!(m & 1)) {
            float2 a = sc[m >> 1], b2 = sc[(m + 64) >> 1];
            S = b2.x - a.x;  Q = b2.y - a.y;
        } else {
            float xa = xs[m - 1], xb2 = xs[m + 63];
            float2 a = sc[(m - 1) >> 1], b2 = sc[(m + 63) >> 1];
            S = (b2.x + xb2) - (a.x + xa);
            Q = (b2.y + xb2 * xb2) - (a.y + xa * xa);
        }
        float mu  = S * (1.0f / 64.0f);
        float var = fmaxf(Q - S * mu, 0.0f) * (1.0f / 63.0f);
        float inv = 1.0f / (sqrtf(var) + 1e-6f);
        ((float*)(sm + OFF_INV))[tid] = inv;
        ((float*)(sm + OFF_MUI))[tid] = mu * inv;
    }
    __syncthreads();

    // ---- A-fragment register cache (shared by both N-passes) ----
    const int Rw = wid << 5;   // warp row base within tile
    const int vb = Rw + g + ct;
    float2 v[11];
#pragma unroll
    for (int j = 0; j < 11; ++j) {
        v[j].x = xs[vb + 8 * j];
        v[j].y = xs[vb + 8 * j + 4];
    }

    const float* Ss  = (const float*)(sm + OFF_S);
    const float* bs  = (const float*)(sm + OFF_BV);
    const float* inv = (const float*)(sm + OFF_INV);
    const float* mui = (const float*)(sm + OFF_MUI);
    float* stw  = (float*)(sm + OFF_STAGE + wid * WSTAGE);
    float* outb = out + (size_t)batch * LOUT * Kn;

    // ---- two N-passes of 32 cols: 32 accums live, occ 3 CTAs/SM ----
#pragma unroll
    for (int p = 0; p < 2; ++p) {
        float c[2][4][4];
#pragma unroll
        for (int mb = 0; mb < 2; ++mb)
#pragma unroll
            for (int nb = 0; nb < 4; ++nb)
#pragma unroll
                for (int r = 0; r < 4; ++r) c[mb][nb][r] = 0.0f;

#pragma unroll
        for (int kk2 = 0; kk2 < 4; ++kk2) {
            const int k0 = 2 * kk2;
#pragma unroll
            for (int nb = 0; nb < 4; ++nb) {
                int n = (p << 5) + (nb << 3) + g;
                float4 bb = *(const float4*)(sm + OFF_W + n * 320 + kk2 * 64 + ct * 16);
                uint32_t b0 = __float_as_uint(bb.x), b1 = __float_as_uint(bb.y);
                uint32_t b2 = __float_as_uint(bb.z), b3 = __float_as_uint(bb.w);
                mma_tf32(c[0][nb], __float_as_uint(v[k0].x),     __float_as_uint(v[k0 + 1].x),
                                   __float_as_uint(v[k0].y),     __float_as_uint(v[k0 + 1].y), b0, b1);
                mma_tf32(c[0][nb], __float_as_uint(v[k0 + 1].x), __float_as_uint(v[k0 + 2].x),
                                   __float_as_uint(v[k0 + 1].y), __float_as_uint(v[k0 + 2].y), b2, b3);
                mma_tf32(c[1][nb], __float_as_uint(v[k0 + 2].x), __float_as_uint(v[k0 + 3].x),
                                   __float_as_uint(v[k0 + 2].y), __float_as_uint(v[k0 + 3].y), b0, b1);
                mma_tf32(c[1][nb], __float_as_uint(v[k0 + 3].x), __float_as_uint(v[k0 + 4].x),
                                   __float_as_uint(v[k0 + 3].y), __float_as_uint(v[k0 + 4].y), b2, b3);
            }
        }

        // ---- epilogue pass p: stride-40 staging (STS.64/LDS.128 clean) ----
#pragma unroll
        for (int mb = 0; mb < 2; ++mb) {
            const int rA = Rw + (mb << 4) + g;
            const float iA = inv[rA],     mA = mui[rA];
            const float iB = inv[rA + 8], mB = mui[rA + 8];
            const int srow = (mb << 4) + g;      // warp-local staging row
#pragma unroll
            for (int nb = 0; nb < 4; ++nb) {
                int lcol = (nb << 3) + (ct << 1);        // 0..31
                int gcol = (p << 5) + lcol;
                float2 S2 = *(const float2*)(Ss + gcol);
                float2 b2 = *(const float2*)(bs + gcol);
                float2 yA, yB;
                yA.x = fmaxf(fmaf(c[mb][nb][0], iA, fmaf(-mA, S2.x, b2.x)), 0.0f);
                yA.y = fmaxf(fmaf(c[mb][nb][1], iA, fmaf(-mA, S2.y, b2.y)), 0.0f);
                yB.x = fmaxf(fmaf(c[mb][nb][2], iB, fmaf(-mB, S2.x, b2.x)), 0.0f);
                yB.y = fmaxf(fmaf(c[mb][nb][3], iB, fmaf(-mB, S2.y, b2.y)), 0.0f);
                *(float2*)(stw + srow * 40 + lcol)       = yA;
                *(float2*)(stw + (srow + 8) * 40 + lcol) = yB;
            }
        }
        __syncwarp();

        // dense streaming stores: 4 rows x 128B per instruction
#pragma unroll
        for (int i = 0; i < 8; ++i) {
            int row  = (i << 2) + (lid >> 3);
            int quad = lid & 7;
            int gr = t0 + Rw + row;
            if (gr < LOUT) {
                float4 val = *(const float4*)(stw + row * 40 + (quad << 2));
                __stcs((float4*)(outb + (size_t)gr * Kn + (p << 5) + (quad << 2)), val);
            }
        }
        __syncwarp();
    }
}

extern "C" void kernel_launch(void* const* d_in, const int* in_sizes, int n_in,
                              void* d_out, int out_size) {
    const float* x  = (const float*)d_in[0];
    const float* W  = (const float*)d_in[1];
    const float* bv = (const float*)d_in[2];
    float* out = (float*)d_out;

    long long expected = (long long)Bn * LOUT * Kn;
    int extra = ((long long)out_size > expected)
                    ? (int)((long long)out_size - expected) : 0;

    prep_kernel<<<9, 256>>>(W, out, expected, extra);

    cudaFuncSetAttribute(hankel_filterbank_kernel,
                         cudaFuncAttributeMaxDynamicSharedMemorySize, SMEM_BYTES);
    hankel_filterbank_kernel<<<NTILES * Bn, THREADS, SMEM_BYTES>>>(x, bv, out);
}